// round 1
// baseline (speedup 1.0000x reference)
#include <cuda_runtime.h>

#define S_  512
#define B_  64
#define C_  1024
#define V_  10
#define TS_ 128
#define LN_EPS_ 1e-5f

// Scratch (allocation-free rule: __device__ globals)
__device__ float g_P[(size_t)S_ * B_ * TS_];   // pos used at step t   [t][b][l]  (16 MB)
__device__ float g_d[(size_t)S_ * B_ * 3];     // softmax directions   [t][b][k]
__device__ float g_w[(size_t)S_ * B_];         // write gate           [t][b]
__device__ float g_tape[(size_t)TS_ * B_ * C_];// final tape           [l][b][c]  (32 MB)

// ---------------------------------------------------------------------------
// Phase A: heads.  dir = softmax(v @ Wd^T + bd), w = sigmoid(v @ Wr[1] + br[1])
// One warp per (s,b) row. Weights staged in smem. HBM-bound (reads values once).
// ---------------------------------------------------------------------------
__global__ void __launch_bounds__(256) heads_kernel(
    const float* __restrict__ vals,
    const float* __restrict__ Wd, const float* __restrict__ bd,
    const float* __restrict__ Wr, const float* __restrict__ br)
{
    __shared__ float sW[4 * C_];  // rows 0..2 = Wd, row 3 = Wr[1]
    int tid = threadIdx.x;
    for (int i = tid; i < 3 * C_; i += 256) sW[i] = Wd[i];
    for (int i = tid; i < C_;     i += 256) sW[3 * C_ + i] = Wr[C_ + i];
    __syncthreads();

    int warp = tid >> 5, lane = tid & 31;
    int row = blockIdx.x * 8 + warp;               // row = s*B + b
    const float4* v4 = reinterpret_cast<const float4*>(vals + (size_t)row * C_);
    const float4* w4 = reinterpret_cast<const float4*>(sW);

    float a0 = 0.f, a1 = 0.f, a2 = 0.f, a3 = 0.f;
    for (int i = lane; i < C_ / 4; i += 32) {
        float4 v = v4[i];
        float4 w;
        w = w4[i];       a0 += v.x*w.x + v.y*w.y + v.z*w.z + v.w*w.w;
        w = w4[256 + i]; a1 += v.x*w.x + v.y*w.y + v.z*w.z + v.w*w.w;
        w = w4[512 + i]; a2 += v.x*w.x + v.y*w.y + v.z*w.z + v.w*w.w;
        w = w4[768 + i]; a3 += v.x*w.x + v.y*w.y + v.z*w.z + v.w*w.w;
    }
    #pragma unroll
    for (int o = 16; o; o >>= 1) {
        a0 += __shfl_xor_sync(0xffffffffu, a0, o);
        a1 += __shfl_xor_sync(0xffffffffu, a1, o);
        a2 += __shfl_xor_sync(0xffffffffu, a2, o);
        a3 += __shfl_xor_sync(0xffffffffu, a3, o);
    }
    if (lane == 0) {
        float z0 = a0 + bd[0], z1 = a1 + bd[1], z2 = a2 + bd[2];
        float m  = fmaxf(z0, fmaxf(z1, z2));
        float e0 = expf(z0 - m), e1 = expf(z1 - m), e2 = expf(z2 - m);
        float inv = 1.f / (e0 + e1 + e2);
        g_d[(size_t)row * 3 + 0] = e0 * inv;
        g_d[(size_t)row * 3 + 1] = e1 * inv;
        g_d[(size_t)row * 3 + 2] = e2 * inv;
        g_w[row] = 1.f / (1.f + expf(-(a3 + br[1])));
    }
}

// ---------------------------------------------------------------------------
// Phase B: pos evolution. One warp per batch; each lane owns 4 tape slots in
// registers; circular neighbors via shuffles. Stores pos BEFORE update (the
// pos the scan step uses).  new[l] = p[l+1]*d0 + p[l]*d1 + p[l-1]*d2 (mod TS)
// ---------------------------------------------------------------------------
__global__ void __launch_bounds__(256) pos_kernel()
{
    int warp = threadIdx.x >> 5, lane = threadIdx.x & 31;
    int b = blockIdx.x * 8 + warp;
    float p0 = (lane == 0) ? 1.f : 0.f, p1 = 0.f, p2 = 0.f, p3 = 0.f;

    for (int t = 0; t < S_; t++) {
        float4* dst = reinterpret_cast<float4*>(g_P + ((size_t)t * B_ + b) * TS_);
        dst[lane] = make_float4(p0, p1, p2, p3);
        const float* dd = g_d + ((size_t)t * B_ + b) * 3;
        float d0 = dd[0], d1 = dd[1], d2 = dd[2];
        float lw = __shfl_sync(0xffffffffu, p3, (lane + 31) & 31); // p[l-1] wrap
        float rw = __shfl_sync(0xffffffffu, p0, (lane + 1)  & 31); // p[l+1] wrap
        float n0 = p1 * d0 + p0 * d1 + lw * d2;
        float n1 = p2 * d0 + p1 * d1 + p0 * d2;
        float n2 = p3 * d0 + p2 * d1 + p1 * d2;
        float n3 = rw * d0 + p3 * d1 + p2 * d2;
        p0 = n0; p1 = n1; p2 = n2; p3 = n3;
    }
}

// ---------------------------------------------------------------------------
// Phase C: tape scan. Block = one (batch, 128-channel chunk). Each thread owns
// tape[0..127] for one channel in registers. pos broadcast from smem
// (double-buffered, 1 barrier/step); next step's pos/v/w prefetched into regs
// before the compute so the global latency hides under ~256 FFMAs.
// ---------------------------------------------------------------------------
__global__ void __launch_bounds__(128, 3) scan_kernel(const float* __restrict__ vals)
{
    __shared__ float spos[2][TS_];
    int tid = threadIdx.x;
    int b   = blockIdx.x >> 3;
    int c   = ((blockIdx.x & 7) << 7) + tid;

    const float* Pb = g_P + (size_t)b * TS_;        // +t*B*TS
    const float* vb = vals + (size_t)b * C_ + c;    // +t*B*C
    const float* wb = g_w + b;                      // +t*B

    float tp[TS_];
    #pragma unroll
    for (int l = 0; l < TS_; l++) tp[l] = 0.f;

    spos[0][tid] = Pb[tid];
    float curv = vb[0];
    float curw = wb[0];
    __syncthreads();

    for (int t = 0; t < S_; t++) {
        int cur = t & 1;
        // Prefetch next step's operands (overlaps the FMA block below)
        float np = 0.f, nv = 0.f, nw = 0.f;
        if (t + 1 < S_) {
            np = Pb[(size_t)(t + 1) * (B_ * TS_) + tid];
            nv = vb[(size_t)(t + 1) * (B_ * C_)];
            nw = wb[(size_t)(t + 1) * B_];
        }
        const float4* sp = reinterpret_cast<const float4*>(spos[cur]);
        float u0 = 0.f, u1 = 0.f, u2 = 0.f, u3 = 0.f;
        #pragma unroll
        for (int i = 0; i < TS_ / 4; i++) {
            float4 p = sp[i];
            u0 += tp[4*i + 0] * p.x;
            u1 += tp[4*i + 1] * p.y;
            u2 += tp[4*i + 2] * p.z;
            u3 += tp[4*i + 3] * p.w;
        }
        float a = curw * (curv - ((u0 + u1) + (u2 + u3)));
        #pragma unroll
        for (int i = 0; i < TS_ / 4; i++) {
            float4 p = sp[i];
            tp[4*i + 0] += p.x * a;
            tp[4*i + 1] += p.y * a;
            tp[4*i + 2] += p.z * a;
            tp[4*i + 3] += p.w * a;
        }
        spos[cur ^ 1][tid] = np;
        curv = nv; curw = nw;
        __syncthreads();
    }

    #pragma unroll
    for (int l = 0; l < TS_; l++)
        g_tape[((size_t)l * B_ + b) * C_ + c] = tp[l];
}

// ---------------------------------------------------------------------------
// Phase D: LayerNorm + out = h @ Wo^T + bo.  Wo (40KB) staged in smem, 16 rows
// per block to amortize.  out is [TS, B, V] fp32.
// ---------------------------------------------------------------------------
__global__ void __launch_bounds__(256) decode_kernel(
    const float* __restrict__ ln_g, const float* __restrict__ ln_b,
    const float* __restrict__ Wo,   const float* __restrict__ bo,
    float* __restrict__ out)
{
    __shared__ float sWo[V_ * C_];     // 40 KB
    __shared__ float sred[2][8];
    __shared__ float sv[8][V_];
    __shared__ float smv[2];

    int tid = threadIdx.x, lane = tid & 31, warp = tid >> 5;
    for (int i = tid; i < V_ * C_; i += 256) sWo[i] = Wo[i];
    float4 g4 = reinterpret_cast<const float4*>(ln_g)[tid];
    float4 e4 = reinterpret_cast<const float4*>(ln_b)[tid];
    __syncthreads();

    for (int j = 0; j < 16; j++) {
        int row = blockIdx.x * 16 + j;   // row = l*B + b
        float4 x = reinterpret_cast<const float4*>(g_tape)[(size_t)row * (C_ / 4) + tid];
        float s = x.x + x.y + x.z + x.w;
        float q = x.x*x.x + x.y*x.y + x.z*x.z + x.w*x.w;
        #pragma unroll
        for (int o = 16; o; o >>= 1) {
            s += __shfl_xor_sync(0xffffffffu, s, o);
            q += __shfl_xor_sync(0xffffffffu, q, o);
        }
        if (lane == 0) { sred[0][warp] = s; sred[1][warp] = q; }
        __syncthreads();
        if (tid == 0) {
            float ts = 0.f, tq = 0.f;
            #pragma unroll
            for (int k = 0; k < 8; k++) { ts += sred[0][k]; tq += sred[1][k]; }
            float mu = ts * (1.f / C_);
            smv[0] = mu;
            smv[1] = rsqrtf(tq * (1.f / C_) - mu * mu + LN_EPS_);
        }
        __syncthreads();
        float mu = smv[0], rstd = smv[1];
        float4 h;
        h.x = (x.x - mu) * rstd * g4.x + e4.x;
        h.y = (x.y - mu) * rstd * g4.y + e4.y;
        h.z = (x.z - mu) * rstd * g4.z + e4.z;
        h.w = (x.w - mu) * rstd * g4.w + e4.w;
        #pragma unroll
        for (int v = 0; v < V_; v++) {
            float4 w = reinterpret_cast<const float4*>(sWo)[v * (C_ / 4) + tid];
            float pp = h.x*w.x + h.y*w.y + h.z*w.z + h.w*w.w;
            #pragma unroll
            for (int o = 16; o; o >>= 1) pp += __shfl_xor_sync(0xffffffffu, pp, o);
            if (lane == 0) sv[warp][v] = pp;
        }
        __syncthreads();
        if (tid < V_) {
            float acc = bo[tid];
            #pragma unroll
            for (int k = 0; k < 8; k++) acc += sv[k][tid];
            out[(size_t)row * V_ + tid] = acc;
        }
        __syncthreads();
    }
}

// ---------------------------------------------------------------------------
extern "C" void kernel_launch(void* const* d_in, const int* in_sizes, int n_in,
                              void* d_out, int out_size)
{
    const float* vals = (const float*)d_in[0];
    const float* Wd   = (const float*)d_in[1];
    const float* bd   = (const float*)d_in[2];
    const float* Wr   = (const float*)d_in[3];
    const float* br   = (const float*)d_in[4];
    const float* lng  = (const float*)d_in[5];
    const float* lnb  = (const float*)d_in[6];
    const float* Wo   = (const float*)d_in[7];
    const float* bo   = (const float*)d_in[8];
    float* out = (float*)d_out;

    heads_kernel<<<(S_ * B_) / 8, 256>>>(vals, Wd, bd, Wr, br);
    pos_kernel<<<B_ / 8, 256>>>();
    scan_kernel<<<B_ * (C_ / TS_), 128>>>(vals);
    decode_kernel<<<(TS_ * B_) / 16, 256>>>(lng, lnb, Wo, bo, out);
}

// round 2
// speedup vs baseline: 2.2676x; 2.2676x over previous
#include <cuda_runtime.h>

#define S_  512
#define B_  64
#define C_  1024
#define V_  10
#define TS_ 128
#define LN_EPS_ 1e-5f

// Scratch (allocation-free rule: __device__ globals)
__device__ float  g_P[(size_t)S_ * B_ * TS_];    // pos used at step t  [t][b][l] (16 MB)
__device__ float4 g_hd[(size_t)S_ * B_];         // (d0,d1,d2,w) per (t,b)
__device__ float  g_dot[(size_t)S_ * B_];        // dot_t = p_t . p_{t+1}   [t][b]
__device__ float  g_tape[(size_t)TS_ * B_ * C_]; // final tape [l][b][c] (32 MB)

// ---- packed fp32x2 helpers (sm_103a dual fp32 pipe; ptxas never auto-fuses) ----
__device__ __forceinline__ unsigned long long fma2(unsigned long long a,
                                                   unsigned long long b,
                                                   unsigned long long c) {
    unsigned long long d;
    asm("fma.rn.f32x2 %0, %1, %2, %3;" : "=l"(d) : "l"(a), "l"(b), "l"(c));
    return d;
}
__device__ __forceinline__ unsigned long long pk2(float lo, float hi) {
    unsigned long long r;
    asm("mov.b64 %0, {%1, %2};" : "=l"(r) : "f"(lo), "f"(hi));
    return r;
}
__device__ __forceinline__ float2 upk2(unsigned long long x) {
    float2 r;
    asm("mov.b64 {%0, %1}, %2;" : "=f"(r.x), "=f"(r.y) : "l"(x));
    return r;
}

// ---------------------------------------------------------------------------
// Phase A: heads. dir = softmax(v@Wd^T+bd), w = sigmoid(v@Wr[1]+br[1]).
// One warp per (s,b) row; writes packed float4 (d0,d1,d2,w).
// ---------------------------------------------------------------------------
__global__ void __launch_bounds__(256) heads_kernel(
    const float* __restrict__ vals,
    const float* __restrict__ Wd, const float* __restrict__ bd,
    const float* __restrict__ Wr, const float* __restrict__ br)
{
    __shared__ float sW[4 * C_];  // rows 0..2 = Wd, row 3 = Wr[1]
    int tid = threadIdx.x;
    for (int i = tid; i < 3 * C_; i += 256) sW[i] = Wd[i];
    for (int i = tid; i < C_;     i += 256) sW[3 * C_ + i] = Wr[C_ + i];
    __syncthreads();

    int warp = tid >> 5, lane = tid & 31;
    int row = blockIdx.x * 8 + warp;               // row = t*B + b
    const float4* v4 = reinterpret_cast<const float4*>(vals + (size_t)row * C_);
    const float4* w4 = reinterpret_cast<const float4*>(sW);

    float a0 = 0.f, a1 = 0.f, a2 = 0.f, a3 = 0.f;
    for (int i = lane; i < C_ / 4; i += 32) {
        float4 v = v4[i];
        float4 w;
        w = w4[i];       a0 += v.x*w.x + v.y*w.y + v.z*w.z + v.w*w.w;
        w = w4[256 + i]; a1 += v.x*w.x + v.y*w.y + v.z*w.z + v.w*w.w;
        w = w4[512 + i]; a2 += v.x*w.x + v.y*w.y + v.z*w.z + v.w*w.w;
        w = w4[768 + i]; a3 += v.x*w.x + v.y*w.y + v.z*w.z + v.w*w.w;
    }
    #pragma unroll
    for (int o = 16; o; o >>= 1) {
        a0 += __shfl_xor_sync(0xffffffffu, a0, o);
        a1 += __shfl_xor_sync(0xffffffffu, a1, o);
        a2 += __shfl_xor_sync(0xffffffffu, a2, o);
        a3 += __shfl_xor_sync(0xffffffffu, a3, o);
    }
    if (lane == 0) {
        float z0 = a0 + bd[0], z1 = a1 + bd[1], z2 = a2 + bd[2];
        float m  = fmaxf(z0, fmaxf(z1, z2));
        float e0 = expf(z0 - m), e1 = expf(z1 - m), e2 = expf(z2 - m);
        float inv = 1.f / (e0 + e1 + e2);
        float wg  = 1.f / (1.f + expf(-(a3 + br[1])));
        g_hd[row] = make_float4(e0 * inv, e1 * inv, e2 * inv, wg);
    }
}

// ---------------------------------------------------------------------------
// Phase B: pos evolution. One warp per batch, 4 slots/lane, shuffles for the
// circular neighbors. Unroll-4 with a register ring prefetching g_hd so the
// 250-cyc L2 load never sits on the serial chain.
// ---------------------------------------------------------------------------
__global__ void __launch_bounds__(256) pos_kernel()
{
    int warp = threadIdx.x >> 5, lane = threadIdx.x & 31;
    int b = blockIdx.x * 8 + warp;
    float p0 = (lane == 0) ? 1.f : 0.f, p1 = 0.f, p2 = 0.f, p3 = 0.f;

    float4 D0 = g_hd[0 * B_ + b];
    float4 D1 = g_hd[1 * B_ + b];
    float4 D2 = g_hd[2 * B_ + b];
    float4 D3 = g_hd[3 * B_ + b];

    for (int t = 0; t < S_; t += 4) {
        #pragma unroll
        for (int k = 0; k < 4; k++) {
            int tt = t + k;
            float4* dst = reinterpret_cast<float4*>(g_P + ((size_t)tt * B_ + b) * TS_);
            dst[lane] = make_float4(p0, p1, p2, p3);
            float4 Dk = (k == 0) ? D0 : (k == 1) ? D1 : (k == 2) ? D2 : D3;
            float4 Dn = g_hd[(size_t)min(tt + 4, S_ - 1) * B_ + b];
            if (k == 0) D0 = Dn; else if (k == 1) D1 = Dn; else if (k == 2) D2 = Dn; else D3 = Dn;
            float d0 = Dk.x, d1 = Dk.y, d2 = Dk.z;
            float lw = __shfl_sync(0xffffffffu, p3, (lane + 31) & 31);
            float rw = __shfl_sync(0xffffffffu, p0, (lane + 1)  & 31);
            float n0 = p1 * d0 + p0 * d1 + lw * d2;
            float n1 = p2 * d0 + p1 * d1 + p0 * d2;
            float n2 = p3 * d0 + p2 * d1 + p1 * d2;
            float n3 = rw * d0 + p3 * d1 + p2 * d2;
            p0 = n0; p1 = n1; p2 = n2; p3 = n3;
        }
    }
}

// ---------------------------------------------------------------------------
// Phase B2: Gram scalars dot[t][b] = p_t . p_{t+1}. One warp per (t,b) row.
// ---------------------------------------------------------------------------
__global__ void __launch_bounds__(256) dot_kernel()
{
    int warp = blockIdx.x * 8 + (threadIdx.x >> 5);   // warp = t*B + b
    int lane = threadIdx.x & 31;
    int t = warp / B_, b = warp % B_;
    int t1 = min(t + 1, S_ - 1);
    const float4* pa = reinterpret_cast<const float4*>(g_P + ((size_t)t  * B_ + b) * TS_);
    const float4* pb = reinterpret_cast<const float4*>(g_P + ((size_t)t1 * B_ + b) * TS_);
    float4 x = pa[lane], y = pb[lane];
    float d = x.x*y.x + x.y*y.y + x.z*y.z + x.w*y.w;
    #pragma unroll
    for (int o = 16; o; o >>= 1) d += __shfl_xor_sync(0xffffffffu, d, o);
    if (lane == 0) g_dot[warp] = d;
}

// ---------------------------------------------------------------------------
// Phase C: tape scan. Block = (batch, 128-channel chunk), 256 threads:
// half = tid>>7 owns tape slots [half*64, half*64+64) for channel tid&127.
// Deferred reduction: u_{t+1} = sum(tape_t * p_{t+1}) + a_t * dot_t, so each
// step is ONE fused loop of packed f32x2 FMAs with a known at entry.
// pos staged in a 4-deep smem ring; one barrier per step.
// ---------------------------------------------------------------------------
__global__ void __launch_bounds__(256, 2) scan_kernel(const float* __restrict__ vals)
{
    __shared__ __align__(16) float spos[4][TS_];
    __shared__ float ssum[2][256];

    int tid  = threadIdx.x;
    int half = tid >> 7;
    int cl   = tid & 127;
    int b    = blockIdx.x >> 3;
    int c    = ((blockIdx.x & 7) << 7) + cl;

    const float* Pb = g_P + (size_t)b * TS_;                 // + t*B*TS
    const float* vb = vals + (size_t)b * C_ + c;             // + t*B*C
    const float* hw = reinterpret_cast<const float*>(g_hd) + (size_t)b * 4 + 3;  // + t*B*4
    const float* db = g_dot + b;                             // + t*B

    unsigned long long tp[32];
    #pragma unroll
    for (int j = 0; j < 32; j++) tp[j] = 0ull;

    // preload pos rows 0..3 into the ring
    for (int k = tid; k < 4 * TS_; k += 256) {
        int t = k >> 7, l = k & 127;
        spos[t][l] = Pb[(size_t)t * (B_ * TS_) + l];
    }
    // pos prefetch pipeline (p4, p5 in flight)
    float npA = 0.f, npB = 0.f;
    if (tid < 128) {
        npA = Pb[(size_t)4 * (B_ * TS_) + tid];
        npB = Pb[(size_t)5 * (B_ * TS_) + tid];
    }
    // scalar pipelines
    float v0 = vb[0];
    float w0 = hw[0];
    float a  = w0 * v0;                      // a_0 = w_0 * v_0 (tape = 0)
    float vA = vb[(size_t)1 * (B_ * C_)];
    float vB = vb[(size_t)2 * (B_ * C_)];
    float wA = hw[(size_t)1 * (B_ * 4)];
    float wB = hw[(size_t)2 * (B_ * 4)];
    float dA = db[0];
    float dB = db[B_];
    __syncthreads();

    for (int t = 0; t < S_; t++) {
        unsigned long long a2 = pk2(a, a);
        unsigned long long s0 = 0ull, s1 = 0ull;
        const ulonglong2* pn = reinterpret_cast<const ulonglong2*>(spos[(t + 1) & 3]) + half * 16;
        const ulonglong2* pc = reinterpret_cast<const ulonglong2*>(spos[t & 3])       + half * 16;
        #pragma unroll
        for (int i = 0; i < 16; i++) {
            ulonglong2 n = pn[i];
            ulonglong2 p = pc[i];
            s0 = fma2(tp[2*i],     n.x, s0);          // reads pre-update tape
            s1 = fma2(tp[2*i + 1], n.y, s1);
            tp[2*i]     = fma2(p.x, a2, tp[2*i]);
            tp[2*i + 1] = fma2(p.y, a2, tp[2*i + 1]);
        }
        float2 f0 = upk2(s0), f1 = upk2(s1);
        float sm = (f0.x + f0.y) + (f1.x + f1.y);
        ssum[t & 1][tid] = sm;
        __syncthreads();
        // rotate pos ring: buf[t&3] (= p_t, fully consumed) <- p_{t+4}
        if (tid < 128) {
            spos[t & 3][tid] = npA;
            npA = npB;
            npB = Pb[(size_t)min(t + 6, S_ - 1) * (B_ * TS_) + tid];
        }
        float sp = ssum[t & 1][tid ^ 128];
        float u  = sm + sp + a * dA;          // u_{t+1}
        a = wA * (vA - u);                    // a_{t+1}
        dA = dB; dB = db[(size_t)min(t + 2, S_ - 1) * B_];
        vA = vB; vB = vb[(size_t)min(t + 3, S_ - 1) * (B_ * C_)];
        wA = wB; wB = hw[(size_t)min(t + 3, S_ - 1) * (B_ * 4)];
    }

    #pragma unroll
    for (int j = 0; j < 32; j++) {
        float2 f = upk2(tp[j]);
        int l = half * 64 + 2 * j;
        g_tape[((size_t)l       * B_ + b) * C_ + c] = f.x;
        g_tape[((size_t)(l + 1) * B_ + b) * C_ + c] = f.y;
    }
}

// ---------------------------------------------------------------------------
// Phase D: LayerNorm + out = h @ Wo^T + bo.  Wo (40KB) in smem, 16 rows/block.
// ---------------------------------------------------------------------------
__global__ void __launch_bounds__(256) decode_kernel(
    const float* __restrict__ ln_g, const float* __restrict__ ln_b,
    const float* __restrict__ Wo,   const float* __restrict__ bo,
    float* __restrict__ out)
{
    __shared__ float sWo[V_ * C_];     // 40 KB
    __shared__ float sred[2][8];
    __shared__ float sv[8][V_];
    __shared__ float smv[2];

    int tid = threadIdx.x, lane = tid & 31, warp = tid >> 5;
    for (int i = tid; i < V_ * C_; i += 256) sWo[i] = Wo[i];
    float4 g4 = reinterpret_cast<const float4*>(ln_g)[tid];
    float4 e4 = reinterpret_cast<const float4*>(ln_b)[tid];
    __syncthreads();

    for (int j = 0; j < 16; j++) {
        int row = blockIdx.x * 16 + j;   // row = l*B + b
        float4 x = reinterpret_cast<const float4*>(g_tape)[(size_t)row * (C_ / 4) + tid];
        float s = x.x + x.y + x.z + x.w;
        float q = x.x*x.x + x.y*x.y + x.z*x.z + x.w*x.w;
        #pragma unroll
        for (int o = 16; o; o >>= 1) {
            s += __shfl_xor_sync(0xffffffffu, s, o);
            q += __shfl_xor_sync(0xffffffffu, q, o);
        }
        if (lane == 0) { sred[0][warp] = s; sred[1][warp] = q; }
        __syncthreads();
        if (tid == 0) {
            float ts = 0.f, tq = 0.f;
            #pragma unroll
            for (int k = 0; k < 8; k++) { ts += sred[0][k]; tq += sred[1][k]; }
            float mu = ts * (1.f / C_);
            smv[0] = mu;
            smv[1] = rsqrtf(tq * (1.f / C_) - mu * mu + LN_EPS_);
        }
        __syncthreads();
        float mu = smv[0], rstd = smv[1];
        float4 h;
        h.x = (x.x - mu) * rstd * g4.x + e4.x;
        h.y = (x.y - mu) * rstd * g4.y + e4.y;
        h.z = (x.z - mu) * rstd * g4.z + e4.z;
        h.w = (x.w - mu) * rstd * g4.w + e4.w;
        #pragma unroll
        for (int v = 0; v < V_; v++) {
            float4 w = reinterpret_cast<const float4*>(sWo)[v * (C_ / 4) + tid];
            float pp = h.x*w.x + h.y*w.y + h.z*w.z + h.w*w.w;
            #pragma unroll
            for (int o = 16; o; o >>= 1) pp += __shfl_xor_sync(0xffffffffu, pp, o);
            if (lane == 0) sv[warp][v] = pp;
        }
        __syncthreads();
        if (tid < V_) {
            float acc = bo[tid];
            #pragma unroll
            for (int k = 0; k < 8; k++) acc += sv[k][tid];
            out[(size_t)row * V_ + tid] = acc;
        }
        __syncthreads();
    }
}

// ---------------------------------------------------------------------------
extern "C" void kernel_launch(void* const* d_in, const int* in_sizes, int n_in,
                              void* d_out, int out_size)
{
    const float* vals = (const float*)d_in[0];
    const float* Wd   = (const float*)d_in[1];
    const float* bd   = (const float*)d_in[2];
    const float* Wr   = (const float*)d_in[3];
    const float* br   = (const float*)d_in[4];
    const float* lng  = (const float*)d_in[5];
    const float* lnb  = (const float*)d_in[6];
    const float* Wo   = (const float*)d_in[7];
    const float* bo   = (const float*)d_in[8];
    float* out = (float*)d_out;

    heads_kernel<<<(S_ * B_) / 8, 256>>>(vals, Wd, bd, Wr, br);
    pos_kernel<<<B_ / 8, 256>>>();
    dot_kernel<<<(S_ * B_) / 8, 256>>>();
    scan_kernel<<<B_ * (C_ / TS_), 256>>>(vals);
    decode_kernel<<<(TS_ * B_) / 16, 256>>>(lng, lnb, Wo, bo, out);
}

// round 4
// speedup vs baseline: 3.4241x; 1.5100x over previous
#include <cuda_runtime.h>

#define S_  512
#define B_  64
#define C_  1024
#define V_  10
#define TS_ 128
#define K_  64            // chunk length
#define NQ_ (S_ / K_)     // 8 chunks
#define LN_EPS_ 1e-5f

// Scratch (allocation-free rule: __device__ globals)
__device__ float  g_P[(size_t)S_ * B_ * TS_];     // pos at step t  [t][b][l] (16 MB)
__device__ float4 g_hd[(size_t)S_ * B_];          // (d0,d1,d2,w) per (t,b)
__device__ float  g_G[(size_t)B_ * NQ_ * K_ * K_];// Gram per (b,chunk): [t][tau] (8 MB)
__device__ float  g_tape[(size_t)TS_ * B_ * C_];  // final tape [l][b][c] (32 MB)

// ---- packed fp32x2 helpers ----
__device__ __forceinline__ unsigned long long fma2(unsigned long long a,
                                                   unsigned long long b,
                                                   unsigned long long c) {
    unsigned long long d;
    asm("fma.rn.f32x2 %0, %1, %2, %3;" : "=l"(d) : "l"(a), "l"(b), "l"(c));
    return d;
}
__device__ __forceinline__ unsigned long long pk2(float lo, float hi) {
    unsigned long long r;
    asm("mov.b64 %0, {%1, %2};" : "=l"(r) : "f"(lo), "f"(hi));
    return r;
}
__device__ __forceinline__ float2 upk2(unsigned long long x) {
    float2 r;
    asm("mov.b64 {%0, %1}, %2;" : "=f"(r.x), "=f"(r.y) : "l"(x));
    return r;
}
__device__ __forceinline__ void cpa16(void* s, const void* g) {
    unsigned sa = (unsigned)__cvta_generic_to_shared(s);
    asm volatile("cp.async.ca.shared.global [%0], [%1], 16;" :: "r"(sa), "l"(g));
}
__device__ __forceinline__ void cpa_commit_waitall() {
    asm volatile("cp.async.commit_group;");
    asm volatile("cp.async.wait_group 0;" ::: "memory");
}

// ---------------------------------------------------------------------------
// Phase A: heads. dir = softmax(v@Wd^T+bd), w = sigmoid(v@Wr[1]+br[1]).
// ---------------------------------------------------------------------------
__global__ void __launch_bounds__(256) heads_kernel(
    const float* __restrict__ vals,
    const float* __restrict__ Wd, const float* __restrict__ bd,
    const float* __restrict__ Wr, const float* __restrict__ br)
{
    __shared__ float sW[4 * C_];
    int tid = threadIdx.x;
    for (int i = tid; i < 3 * C_; i += 256) sW[i] = Wd[i];
    for (int i = tid; i < C_;     i += 256) sW[3 * C_ + i] = Wr[C_ + i];
    __syncthreads();

    int warp = tid >> 5, lane = tid & 31;
    int row = blockIdx.x * 8 + warp;               // row = t*B + b
    const float4* v4 = reinterpret_cast<const float4*>(vals + (size_t)row * C_);
    const float4* w4 = reinterpret_cast<const float4*>(sW);

    float a0 = 0.f, a1 = 0.f, a2 = 0.f, a3 = 0.f;
    for (int i = lane; i < C_ / 4; i += 32) {
        float4 v = v4[i];
        float4 w;
        w = w4[i];       a0 += v.x*w.x + v.y*w.y + v.z*w.z + v.w*w.w;
        w = w4[256 + i]; a1 += v.x*w.x + v.y*w.y + v.z*w.z + v.w*w.w;
        w = w4[512 + i]; a2 += v.x*w.x + v.y*w.y + v.z*w.z + v.w*w.w;
        w = w4[768 + i]; a3 += v.x*w.x + v.y*w.y + v.z*w.z + v.w*w.w;
    }
    #pragma unroll
    for (int o = 16; o; o >>= 1) {
        a0 += __shfl_xor_sync(0xffffffffu, a0, o);
        a1 += __shfl_xor_sync(0xffffffffu, a1, o);
        a2 += __shfl_xor_sync(0xffffffffu, a2, o);
        a3 += __shfl_xor_sync(0xffffffffu, a3, o);
    }
    if (lane == 0) {
        float z0 = a0 + bd[0], z1 = a1 + bd[1], z2 = a2 + bd[2];
        float m  = fmaxf(z0, fmaxf(z1, z2));
        float e0 = expf(z0 - m), e1 = expf(z1 - m), e2 = expf(z2 - m);
        float inv = 1.f / (e0 + e1 + e2);
        float wg  = 1.f / (1.f + expf(-(a3 + br[1])));
        g_hd[row] = make_float4(e0 * inv, e1 * inv, e2 * inv, wg);
    }
}

// ---------------------------------------------------------------------------
// Phase B: pos evolution. One warp per batch, 4 slots/lane, shuffle neighbors.
// ---------------------------------------------------------------------------
__global__ void __launch_bounds__(256) pos_kernel()
{
    int warp = threadIdx.x >> 5, lane = threadIdx.x & 31;
    int b = blockIdx.x * 8 + warp;
    float p0 = (lane == 0) ? 1.f : 0.f, p1 = 0.f, p2 = 0.f, p3 = 0.f;

    float4 D0 = g_hd[0 * B_ + b];
    float4 D1 = g_hd[1 * B_ + b];
    float4 D2 = g_hd[2 * B_ + b];
    float4 D3 = g_hd[3 * B_ + b];

    for (int t = 0; t < S_; t += 4) {
        #pragma unroll
        for (int k = 0; k < 4; k++) {
            int tt = t + k;
            float4* dst = reinterpret_cast<float4*>(g_P + ((size_t)tt * B_ + b) * TS_);
            dst[lane] = make_float4(p0, p1, p2, p3);
            float4 Dk = (k == 0) ? D0 : (k == 1) ? D1 : (k == 2) ? D2 : D3;
            float4 Dn = g_hd[(size_t)min(tt + 4, S_ - 1) * B_ + b];
            if (k == 0) D0 = Dn; else if (k == 1) D1 = Dn; else if (k == 2) D2 = Dn; else D3 = Dn;
            float d0 = Dk.x, d1 = Dk.y, d2 = Dk.z;
            float lw = __shfl_sync(0xffffffffu, p3, (lane + 31) & 31);
            float rw = __shfl_sync(0xffffffffu, p0, (lane + 1)  & 31);
            float n0 = p1 * d0 + p0 * d1 + lw * d2;
            float n1 = p2 * d0 + p1 * d1 + p0 * d2;
            float n2 = p3 * d0 + p2 * d1 + p1 * d2;
            float n3 = rw * d0 + p3 * d1 + p2 * d2;
            p0 = n0; p1 = n1; p2 = n2; p3 = n3;
        }
    }
}

// ---------------------------------------------------------------------------
// Phase B2: per-(b,chunk) Gram matrix G[t][tau] = p_{T0+t} . p_{T0+tau}.
// Symmetric, stored full 64x64. Row-t stores are coalesced over tau.
// ---------------------------------------------------------------------------
__global__ void __launch_bounds__(256) gram_kernel()
{
    __shared__ float sP[K_][132];   // padded rows
    int tid = threadIdx.x;
    int b = blockIdx.x >> 3, q = blockIdx.x & 7;
    int T0 = q * K_;

    for (int idx = tid; idx < K_ * TS_; idx += 256) {
        int t = idx >> 7, l = idx & 127;
        sP[t][l] = g_P[((size_t)(T0 + t) * B_ + b) * TS_ + l];
    }
    __syncthreads();

    int warp = tid >> 5, lane = tid & 31;
    float* gout = g_G + (size_t)blockIdx.x * (K_ * K_);
    for (int tt = 0; tt < 8; tt++) {
        int t = warp * 8 + tt;
        #pragma unroll
        for (int pass = 0; pass < 2; pass++) {
            int tau = lane + pass * 32;
            float d0 = 0.f, d1 = 0.f;
            #pragma unroll 8
            for (int k = 0; k < 32; k++) {
                float4 x = *reinterpret_cast<const float4*>(&sP[t][4 * k]);
                float4 y = *reinterpret_cast<const float4*>(&sP[tau][4 * k]);
                d0 += x.x * y.x + x.y * y.y;
                d1 += x.z * y.z + x.w * y.w;
            }
            gout[t * K_ + tau] = d0 + d1;
        }
    }
}

// ---------------------------------------------------------------------------
// Phase C: chunked tape scan. Block = (batch b, 128-channel group).
// 256 threads: half = tid>>7 owns tape slots [64h, 64h+64) for channel cl.
// Per chunk:  stage P/G/v/w -> smem (cp.async)
//   phase1: s_t = ckpt_tape . p_t   (half0 -> spart, half1 -> sv -= s)
//   phase2: per-channel triangular solve over Gram (tid<128, 8-wide tiles)
//   phase3: tape += sum_t a_t p_t
// 4 barriers per chunk; dense phases are pure FFMA2 + LDS.128-broadcast.
// ---------------------------------------------------------------------------
__global__ void __launch_bounds__(256, 2) scan_kernel(const float* __restrict__ vals)
{
    extern __shared__ float sm[];
    float* sP    = sm;                         // [K_][128]   8192
    float* sG    = sP + K_ * TS_;              // [t][tau]    4096
    float* sv    = sG + K_ * K_;               // [K_][128]   8192  (v -> v-s1 -> a)
    float* spart = sv + K_ * TS_;              // [K_][128]   8192  (half0 partials)
    float* sw    = spart + K_ * TS_;           // [K_]        64

    int tid  = threadIdx.x;
    int half = tid >> 7;
    int cl   = tid & 127;
    int b    = blockIdx.x >> 3;
    int cg   = blockIdx.x & 7;
    int c0   = cg << 7;

    unsigned long long tp[32];
    #pragma unroll
    for (int j = 0; j < 32; j++) tp[j] = 0ull;

    const float* Gbase = g_G + (size_t)(b * NQ_) * (K_ * K_);

    for (int q = 0; q < NQ_; q++) {
        int T0 = q * K_;
        // ---- stage (row = 128 floats = 32 sixteen-byte segs) ----
        #pragma unroll
        for (int i = 0; i < 8; i++) {            // P: 2048 16B segs
            int idx = tid + 256 * i;
            int t = idx >> 5, seg = idx & 31;
            cpa16(sP + t * TS_ + seg * 4,
                  g_P + ((size_t)(T0 + t) * B_ + b) * TS_ + seg * 4);
        }
        #pragma unroll
        for (int i = 0; i < 8; i++) {            // v: 2048 16B segs
            int idx = tid + 256 * i;
            int t = idx >> 5, seg = idx & 31;
            cpa16(sv + t * TS_ + seg * 4,
                  vals + ((size_t)(T0 + t) * B_ + b) * C_ + c0 + seg * 4);
        }
        #pragma unroll
        for (int i = 0; i < 4; i++) {            // G: 1024 16B segs
            int idx = tid + 256 * i;
            cpa16(sG + idx * 4, Gbase + (size_t)q * (K_ * K_) + idx * 4);
        }
        if (tid < K_)
            sw[tid] = reinterpret_cast<const float*>(g_hd)
                        [((size_t)(T0 + tid) * B_ + b) * 4 + 3];
        cpa_commit_waitall();
        __syncthreads();

        // ---- phase 1: ubase ----
        {
            const ulonglong2* prb = reinterpret_cast<const ulonglong2*>(sP) + half * 16;
            for (int t = 0; t < K_; t++) {
                const ulonglong2* pr = prb + t * 32;
                unsigned long long acc0 = 0ull, acc1 = 0ull;
                #pragma unroll
                for (int lg = 0; lg < 16; lg++) {
                    ulonglong2 qv = pr[lg];
                    acc0 = fma2(tp[2 * lg],     qv.x, acc0);
                    acc1 = fma2(tp[2 * lg + 1], qv.y, acc1);
                }
                float2 f0 = upk2(acc0), f1 = upk2(acc1);
                float s = (f0.x + f0.y) + (f1.x + f1.y);
                if (half == 0) spart[t * TS_ + cl] = s;
                else           sv[t * TS_ + cl] -= s;
            }
        }
        __syncthreads();

        // ---- phase 2: triangular solve per channel ----
        if (tid < 128) {
            int c = tid;
            #pragma unroll 1
            for (int i = 0; i < 8; i++) {
                int t0 = i * 8;
                float u[8];
                #pragma unroll
                for (int j = 0; j < 8; j++) u[j] = 0.f;
                for (int tau = 0; tau < t0; tau++) {
                    float at = sv[tau * TS_ + c];
                    float4 Ga = *reinterpret_cast<const float4*>(sG + tau * K_ + t0);
                    float4 Gb = *reinterpret_cast<const float4*>(sG + tau * K_ + t0 + 4);
                    u[0] += at * Ga.x; u[1] += at * Ga.y;
                    u[2] += at * Ga.z; u[3] += at * Ga.w;
                    u[4] += at * Gb.x; u[5] += at * Gb.y;
                    u[6] += at * Gb.z; u[7] += at * Gb.w;
                }
                float at8[8];
                #pragma unroll
                for (int j = 0; j < 8; j++) {
                    int t = t0 + j;
                    float uu = u[j];
                    #pragma unroll
                    for (int jj = 0; jj < 8; jj++)
                        if (jj < j) uu += at8[jj] * sG[(t0 + jj) * K_ + t];
                    float r = sv[t * TS_ + c] - spart[t * TS_ + c];
                    float a = sw[t] * (r - uu);
                    at8[j] = a;
                    sv[t * TS_ + c] = a;
                }
            }
        }
        __syncthreads();

        // ---- phase 3: tape += sum_t a_t p_t ----
        {
            const ulonglong2* prb = reinterpret_cast<const ulonglong2*>(sP) + half * 16;
            for (int t = 0; t < K_; t++) {
                float a = sv[t * TS_ + cl];
                unsigned long long a2 = pk2(a, a);
                const ulonglong2* pr = prb + t * 32;
                #pragma unroll
                for (int lg = 0; lg < 16; lg++) {
                    ulonglong2 qv = pr[lg];
                    tp[2 * lg]     = fma2(qv.x, a2, tp[2 * lg]);
                    tp[2 * lg + 1] = fma2(qv.y, a2, tp[2 * lg + 1]);
                }
            }
        }
        __syncthreads();
    }

    // ---- write final tape ----
    int c = c0 + cl;
    #pragma unroll
    for (int j = 0; j < 32; j++) {
        float2 f = upk2(tp[j]);
        int l = half * 64 + 2 * j;
        g_tape[((size_t)l       * B_ + b) * C_ + c] = f.x;
        g_tape[((size_t)(l + 1) * B_ + b) * C_ + c] = f.y;
    }
}

// ---------------------------------------------------------------------------
// Phase D: LayerNorm + out = h @ Wo^T + bo.
// ---------------------------------------------------------------------------
__global__ void __launch_bounds__(256) decode_kernel(
    const float* __restrict__ ln_g, const float* __restrict__ ln_b,
    const float* __restrict__ Wo,   const float* __restrict__ bo,
    float* __restrict__ out)
{
    __shared__ float sWo[V_ * C_];
    __shared__ float sred[2][8];
    __shared__ float sv2[8][V_];
    __shared__ float smv[2];

    int tid = threadIdx.x, lane = tid & 31, warp = tid >> 5;
    for (int i = tid; i < V_ * C_; i += 256) sWo[i] = Wo[i];
    float4 g4 = reinterpret_cast<const float4*>(ln_g)[tid];
    float4 e4 = reinterpret_cast<const float4*>(ln_b)[tid];
    __syncthreads();

    for (int j = 0; j < 16; j++) {
        int row = blockIdx.x * 16 + j;
        float4 x = reinterpret_cast<const float4*>(g_tape)[(size_t)row * (C_ / 4) + tid];
        float s = x.x + x.y + x.z + x.w;
        float qq = x.x*x.x + x.y*x.y + x.z*x.z + x.w*x.w;
        #pragma unroll
        for (int o = 16; o; o >>= 1) {
            s  += __shfl_xor_sync(0xffffffffu, s, o);
            qq += __shfl_xor_sync(0xffffffffu, qq, o);
        }
        if (lane == 0) { sred[0][warp] = s; sred[1][warp] = qq; }
        __syncthreads();
        if (tid == 0) {
            float ts = 0.f, tq = 0.f;
            #pragma unroll
            for (int k = 0; k < 8; k++) { ts += sred[0][k]; tq += sred[1][k]; }
            float mu = ts * (1.f / C_);
            smv[0] = mu;
            smv[1] = rsqrtf(tq * (1.f / C_) - mu * mu + LN_EPS_);
        }
        __syncthreads();
        float mu = smv[0], rstd = smv[1];
        float4 h;
        h.x = (x.x - mu) * rstd * g4.x + e4.x;
        h.y = (x.y - mu) * rstd * g4.y + e4.y;
        h.z = (x.z - mu) * rstd * g4.z + e4.z;
        h.w = (x.w - mu) * rstd * g4.w + e4.w;
        #pragma unroll
        for (int v = 0; v < V_; v++) {
            float4 w = reinterpret_cast<const float4*>(sWo)[v * (C_ / 4) + tid];
            float pp = h.x*w.x + h.y*w.y + h.z*w.z + h.w*w.w;
            #pragma unroll
            for (int o = 16; o; o >>= 1) pp += __shfl_xor_sync(0xffffffffu, pp, o);
            if (lane == 0) sv2[warp][v] = pp;
        }
        __syncthreads();
        if (tid < V_) {
            float acc = bo[tid];
            #pragma unroll
            for (int k = 0; k < 8; k++) acc += sv2[k][tid];
            out[(size_t)row * V_ + tid] = acc;
        }
        __syncthreads();
    }
}

// ---------------------------------------------------------------------------
extern "C" void kernel_launch(void* const* d_in, const int* in_sizes, int n_in,
                              void* d_out, int out_size)
{
    const float* vals = (const float*)d_in[0];
    const float* Wd   = (const float*)d_in[1];
    const float* bd   = (const float*)d_in[2];
    const float* Wr   = (const float*)d_in[3];
    const float* br   = (const float*)d_in[4];
    const float* lng  = (const float*)d_in[5];
    const float* lnb  = (const float*)d_in[6];
    const float* Wo   = (const float*)d_in[7];
    const float* bo   = (const float*)d_in[8];
    float* out = (float*)d_out;

    const int SMEM_SCAN = (K_ * TS_ + K_ * K_ + K_ * TS_ + K_ * TS_ + K_) * 4;
    cudaFuncSetAttribute(scan_kernel,
                         cudaFuncAttributeMaxDynamicSharedMemorySize, SMEM_SCAN);

    heads_kernel<<<(S_ * B_) / 8, 256>>>(vals, Wd, bd, Wr, br);
    pos_kernel<<<B_ / 8, 256>>>();
    gram_kernel<<<B_ * NQ_, 256>>>();
    scan_kernel<<<B_ * (C_ / TS_), 256, SMEM_SCAN>>>(vals);
    decode_kernel<<<(TS_ * B_) / 16, 256>>>(lng, lnb, Wo, bo, out);
}

// round 5
// speedup vs baseline: 4.8758x; 1.4240x over previous
#include <cuda_runtime.h>

#define S_  512
#define B_  64
#define C_  1024
#define V_  10
#define TS_ 128
#define K_  64            // chunk length
#define NQ_ (S_ / K_)     // 8 chunks
#define G_  8             // group size within chunk
#define LN_EPS_ 1e-5f

typedef unsigned long long ull;

// Scratch (allocation-free rule: __device__ globals)
__device__ float  g_P[(size_t)S_ * B_ * TS_];      // pos at step t [t][b][l] (16 MB)
__device__ float4 g_hd[(size_t)S_ * B_];           // (d0,d1,d2,w) per (t,b)
__device__ float  g_Gd[(size_t)B_ * NQ_ * 8 * 64]; // diag 8x8 Gram blocks (1 MB)
__device__ float  g_tape[(size_t)TS_ * B_ * C_];   // final tape [l][b][c] (32 MB)

// ---- packed fp32x2 helpers ----
__device__ __forceinline__ ull fma2(ull a, ull b, ull c) {
    ull d;
    asm("fma.rn.f32x2 %0, %1, %2, %3;" : "=l"(d) : "l"(a), "l"(b), "l"(c));
    return d;
}
__device__ __forceinline__ ull add2(ull a, ull b) {
    ull d;
    asm("add.rn.f32x2 %0, %1, %2;" : "=l"(d) : "l"(a), "l"(b));
    return d;
}
__device__ __forceinline__ ull pk2(float lo, float hi) {
    ull r;
    asm("mov.b64 %0, {%1, %2};" : "=l"(r) : "f"(lo), "f"(hi));
    return r;
}
__device__ __forceinline__ float2 upk2(ull x) {
    float2 r;
    asm("mov.b64 {%0, %1}, %2;" : "=f"(r.x), "=f"(r.y) : "l"(x));
    return r;
}
__device__ __forceinline__ void cpa16(void* s, const void* g) {
    unsigned sa = (unsigned)__cvta_generic_to_shared(s);
    asm volatile("cp.async.ca.shared.global [%0], [%1], 16;" :: "r"(sa), "l"(g));
}
__device__ __forceinline__ void cpa_commit_waitall() {
    asm volatile("cp.async.commit_group;");
    asm volatile("cp.async.wait_group 0;" ::: "memory");
}

// ---------------------------------------------------------------------------
// Phase A: heads. dir = softmax(v@Wd^T+bd), w = sigmoid(v@Wr[1]+br[1]).
// ---------------------------------------------------------------------------
__global__ void __launch_bounds__(256) heads_kernel(
    const float* __restrict__ vals,
    const float* __restrict__ Wd, const float* __restrict__ bd,
    const float* __restrict__ Wr, const float* __restrict__ br)
{
    __shared__ float sW[4 * C_];
    int tid = threadIdx.x;
    for (int i = tid; i < 3 * C_; i += 256) sW[i] = Wd[i];
    for (int i = tid; i < C_;     i += 256) sW[3 * C_ + i] = Wr[C_ + i];
    __syncthreads();

    int warp = tid >> 5, lane = tid & 31;
    int row = blockIdx.x * 8 + warp;               // row = t*B + b
    const float4* v4 = reinterpret_cast<const float4*>(vals + (size_t)row * C_);
    const float4* w4 = reinterpret_cast<const float4*>(sW);

    float a0 = 0.f, a1 = 0.f, a2 = 0.f, a3 = 0.f;
    for (int i = lane; i < C_ / 4; i += 32) {
        float4 v = v4[i];
        float4 w;
        w = w4[i];       a0 += v.x*w.x + v.y*w.y + v.z*w.z + v.w*w.w;
        w = w4[256 + i]; a1 += v.x*w.x + v.y*w.y + v.z*w.z + v.w*w.w;
        w = w4[512 + i]; a2 += v.x*w.x + v.y*w.y + v.z*w.z + v.w*w.w;
        w = w4[768 + i]; a3 += v.x*w.x + v.y*w.y + v.z*w.z + v.w*w.w;
    }
    #pragma unroll
    for (int o = 16; o; o >>= 1) {
        a0 += __shfl_xor_sync(0xffffffffu, a0, o);
        a1 += __shfl_xor_sync(0xffffffffu, a1, o);
        a2 += __shfl_xor_sync(0xffffffffu, a2, o);
        a3 += __shfl_xor_sync(0xffffffffu, a3, o);
    }
    if (lane == 0) {
        float z0 = a0 + bd[0], z1 = a1 + bd[1], z2 = a2 + bd[2];
        float m  = fmaxf(z0, fmaxf(z1, z2));
        float e0 = expf(z0 - m), e1 = expf(z1 - m), e2 = expf(z2 - m);
        float inv = 1.f / (e0 + e1 + e2);
        float wg  = 1.f / (1.f + expf(-(a3 + br[1])));
        g_hd[row] = make_float4(e0 * inv, e1 * inv, e2 * inv, wg);
    }
}

// ---------------------------------------------------------------------------
// Phase B: pos evolution. One warp per batch, 4 slots/lane, shuffle neighbors.
// ---------------------------------------------------------------------------
__global__ void __launch_bounds__(256) pos_kernel()
{
    int warp = threadIdx.x >> 5, lane = threadIdx.x & 31;
    int b = blockIdx.x * 8 + warp;
    float p0 = (lane == 0) ? 1.f : 0.f, p1 = 0.f, p2 = 0.f, p3 = 0.f;

    float4 D0 = g_hd[0 * B_ + b];
    float4 D1 = g_hd[1 * B_ + b];
    float4 D2 = g_hd[2 * B_ + b];
    float4 D3 = g_hd[3 * B_ + b];

    for (int t = 0; t < S_; t += 4) {
        #pragma unroll
        for (int k = 0; k < 4; k++) {
            int tt = t + k;
            float4* dst = reinterpret_cast<float4*>(g_P + ((size_t)tt * B_ + b) * TS_);
            dst[lane] = make_float4(p0, p1, p2, p3);
            float4 Dk = (k == 0) ? D0 : (k == 1) ? D1 : (k == 2) ? D2 : D3;
            float4 Dn = g_hd[(size_t)min(tt + 4, S_ - 1) * B_ + b];
            if (k == 0) D0 = Dn; else if (k == 1) D1 = Dn; else if (k == 2) D2 = Dn; else D3 = Dn;
            float d0 = Dk.x, d1 = Dk.y, d2 = Dk.z;
            float lw = __shfl_sync(0xffffffffu, p3, (lane + 31) & 31);
            float rw = __shfl_sync(0xffffffffu, p0, (lane + 1)  & 31);
            float n0 = p1 * d0 + p0 * d1 + lw * d2;
            float n1 = p2 * d0 + p1 * d1 + p0 * d2;
            float n2 = p3 * d0 + p2 * d1 + p1 * d2;
            float n3 = rw * d0 + p3 * d1 + p2 * d2;
            p0 = n0; p1 = n1; p2 = n2; p3 = n3;
        }
    }
}

// ---------------------------------------------------------------------------
// Phase B2: diagonal 8x8 Gram blocks only: Gd[b][q][g][jj][j] =
//   p_{T0+8g+jj} . p_{T0+8g+j}.  Tiny (8x less work than full chunk Gram).
// ---------------------------------------------------------------------------
__global__ void __launch_bounds__(256) gramd_kernel()
{
    __shared__ float sPg[K_][132];   // padded rows
    int tid = threadIdx.x;
    int b = blockIdx.x >> 3, q = blockIdx.x & 7;
    int T0 = q * K_;

    for (int idx = tid; idx < K_ * TS_; idx += 256) {
        int t = idx >> 7, l = idx & 127;
        sPg[t][l] = g_P[((size_t)(T0 + t) * B_ + b) * TS_ + l];
    }
    __syncthreads();

    int w = tid >> 5, lane = tid & 31;   // warp w handles group w
    float* out = g_Gd + (size_t)blockIdx.x * 512 + w * 64;
    #pragma unroll
    for (int e = lane; e < 64; e += 32) {
        int jj = e >> 3, j = e & 7;
        const float* ra = sPg[w * 8 + jj];
        const float* rb = sPg[w * 8 + j];
        float d0 = 0.f, d1 = 0.f;
        #pragma unroll 8
        for (int k = 0; k < 32; k++) {
            float4 x = *reinterpret_cast<const float4*>(ra + 4 * k);
            float4 y = *reinterpret_cast<const float4*>(rb + 4 * k);
            d0 += x.x * y.x + x.y * y.y;
            d1 += x.z * y.z + x.w * y.w;
        }
        out[e] = d0 + d1;
    }
}

// ---------------------------------------------------------------------------
// Phase C: chunked tape scan, 2-D register tiling.
// Block = (batch b, 128-channel group). 256 threads as 8(ty) x 32(tx):
//   thread tile = 16 slots (ty*16..+16, as 8 slot-pairs) x 4 channels (tx*4..+4).
// Per 8-step group g within a chunk:
//   phase1: partial u = tape_tile . p_t  -> spart   (4 LDS.128 : 32 FFMA2)
//   reduce: sv[t][c] -= sum_ty spart                (packed f32x2 sweep)
//   solve : eager 8x8 triangular with diag Gram     (128 threads)
//   phase3: tape_tile += p_t (x) a_t                (5 LDS.128 : 32 FFMA2)
// Interleaving phase3 per group makes the tape absorb all earlier groups, so
// no cross-group Gram GEMV is needed (diagonal blocks only).
// ---------------------------------------------------------------------------
__global__ void __launch_bounds__(256, 2) scan_kernel(const float* __restrict__ vals)
{
    extern __shared__ float sm[];
    float* sP    = sm;                 // [64][128]      8192 floats
    float* sv    = sP + K_ * TS_;      // [64][128]      8192 (v -> r -> a)
    float* spart = sv + K_ * TS_;      // [ty8][tl8][128] 8192
    float* sGd   = spart + 8 * G_ * TS_; // [g8][64]     512
    float* sw    = sGd + 8 * 64;       // [64]

    int tid = threadIdx.x;
    int ty  = tid >> 5;                // 0..7 slot group
    int tx  = tid & 31;                // 0..31 channel group
    int b   = blockIdx.x >> 3;
    int cg  = blockIdx.x & 7;
    int c0  = cg << 7;

    const ull NEG1 = pk2(-1.f, -1.f);

    // tape tile regs: tp[sp][c]: slot pair (ty*16+2sp, +1), channel tx*4+c
    ull tp[8][4];
    #pragma unroll
    for (int sp = 0; sp < 8; sp++)
        #pragma unroll
        for (int c = 0; c < 4; c++) tp[sp][c] = 0ull;

    for (int q = 0; q < NQ_; q++) {
        int T0 = q * K_;
        __syncthreads();   // protect sP/sv from previous iteration's readers
        // ---- stage P, v, Gd, w ----
        #pragma unroll
        for (int i = 0; i < 8; i++) {
            int idx = tid + 256 * i;
            int t = idx >> 5, seg = idx & 31;
            cpa16(sP + t * TS_ + seg * 4,
                  g_P + ((size_t)(T0 + t) * B_ + b) * TS_ + seg * 4);
        }
        #pragma unroll
        for (int i = 0; i < 8; i++) {
            int idx = tid + 256 * i;
            int t = idx >> 5, seg = idx & 31;
            cpa16(sv + t * TS_ + seg * 4,
                  vals + ((size_t)(T0 + t) * B_ + b) * C_ + c0 + seg * 4);
        }
        if (tid < 128)
            cpa16(sGd + tid * 4, g_Gd + (size_t)(b * NQ_ + q) * 512 + tid * 4);
        if (tid < K_)
            sw[tid] = g_hd[(size_t)(T0 + tid) * B_ + b].w;
        cpa_commit_waitall();
        __syncthreads();

        for (int g = 0; g < G_; g++) {
            int t0 = g * 8;

            // ---- phase1: partial ubase for the 8 t's of this group ----
            #pragma unroll 1
            for (int tl = 0; tl < 8; tl++) {
                const ull* pr = reinterpret_cast<const ull*>(sP + (t0 + tl) * TS_) + ty * 8;
                ull a0 = 0ull, a1 = 0ull, a2 = 0ull, a3 = 0ull;
                #pragma unroll
                for (int sp = 0; sp < 8; sp++) {
                    ull p = pr[sp];
                    a0 = fma2(p, tp[sp][0], a0);
                    a1 = fma2(p, tp[sp][1], a1);
                    a2 = fma2(p, tp[sp][2], a2);
                    a3 = fma2(p, tp[sp][3], a3);
                }
                float2 f0 = upk2(a0), f1 = upk2(a1), f2 = upk2(a2), f3 = upk2(a3);
                float4 st = make_float4(f0.x + f0.y, f1.x + f1.y,
                                        f2.x + f2.y, f3.x + f3.y);
                *reinterpret_cast<float4*>(spart + ((ty * 8 + tl) * TS_) + tx * 4) = st;
            }
            __syncthreads();

            // ---- reduce partials into sv: r = v - ubase ----
            #pragma unroll
            for (int rr = 0; rr < 2; rr++) {
                int cc = tid + rr * 256;         // ull cell in [0, 512)
                int tl = cc >> 6, cp = cc & 63;
                ull s = *reinterpret_cast<const ull*>(spart + tl * TS_ + cp * 2);
                #pragma unroll
                for (int yy = 1; yy < 8; yy++)
                    s = add2(s, *reinterpret_cast<const ull*>(
                                    spart + (yy * 8 + tl) * TS_ + cp * 2));
                ull* pv = reinterpret_cast<ull*>(sv + (t0 + tl) * TS_ + cp * 2);
                *pv = fma2(s, NEG1, *pv);
            }
            __syncthreads();

            // ---- solve: eager 8x8 triangular, one thread per channel ----
            if (tid < 128) {
                const float* Gg = sGd + g * 64;
                float at[8];
                #pragma unroll
                for (int j = 0; j < 8; j++) {
                    float u = 0.f;
                    #pragma unroll
                    for (int jj = 0; jj < 8; jj++)
                        if (jj < j) u += at[jj] * Gg[jj * 8 + j];
                    float a = sw[t0 + j] * (sv[(t0 + j) * TS_ + tid] - u);
                    at[j] = a;
                    sv[(t0 + j) * TS_ + tid] = a;
                }
            }
            __syncthreads();

            // ---- phase3: tape += p_t (x) a_t for the group ----
            #pragma unroll 1
            for (int tl = 0; tl < 8; tl++) {
                const ull* pr = reinterpret_cast<const ull*>(sP + (t0 + tl) * TS_) + ty * 8;
                float4 av = *reinterpret_cast<const float4*>(sv + (t0 + tl) * TS_ + tx * 4);
                ull b0 = pk2(av.x, av.x), b1 = pk2(av.y, av.y);
                ull b2 = pk2(av.z, av.z), b3 = pk2(av.w, av.w);
                #pragma unroll
                for (int sp = 0; sp < 8; sp++) {
                    ull p = pr[sp];
                    tp[sp][0] = fma2(p, b0, tp[sp][0]);
                    tp[sp][1] = fma2(p, b1, tp[sp][1]);
                    tp[sp][2] = fma2(p, b2, tp[sp][2]);
                    tp[sp][3] = fma2(p, b3, tp[sp][3]);
                }
            }
            // no barrier needed: next phase1 touches only tape regs + sP,
            // and spart writes were consumed two barriers ago.
        }
    }

    // ---- write final tape: 16 coalesced STG.128 per thread ----
    #pragma unroll
    for (int sp = 0; sp < 8; sp++) {
        float2 r0 = upk2(tp[sp][0]), r1 = upk2(tp[sp][1]);
        float2 r2 = upk2(tp[sp][2]), r3 = upk2(tp[sp][3]);
        int l0 = ty * 16 + 2 * sp;
        float4* d0 = reinterpret_cast<float4*>(
            g_tape + ((size_t)l0 * B_ + b) * C_ + c0 + tx * 4);
        float4* d1 = reinterpret_cast<float4*>(
            g_tape + ((size_t)(l0 + 1) * B_ + b) * C_ + c0 + tx * 4);
        *d0 = make_float4(r0.x, r1.x, r2.x, r3.x);
        *d1 = make_float4(r0.y, r1.y, r2.y, r3.y);
    }
}

// ---------------------------------------------------------------------------
// Phase D: LayerNorm + out = h @ Wo^T + bo.
// ---------------------------------------------------------------------------
__global__ void __launch_bounds__(256) decode_kernel(
    const float* __restrict__ ln_g, const float* __restrict__ ln_b,
    const float* __restrict__ Wo,   const float* __restrict__ bo,
    float* __restrict__ out)
{
    __shared__ float sWo[V_ * C_];
    __shared__ float sred[2][8];
    __shared__ float sv2[8][V_];
    __shared__ float smv[2];

    int tid = threadIdx.x, lane = tid & 31, warp = tid >> 5;
    for (int i = tid; i < V_ * C_; i += 256) sWo[i] = Wo[i];
    float4 g4 = reinterpret_cast<const float4*>(ln_g)[tid];
    float4 e4 = reinterpret_cast<const float4*>(ln_b)[tid];
    __syncthreads();

    for (int j = 0; j < 16; j++) {
        int row = blockIdx.x * 16 + j;
        float4 x = reinterpret_cast<const float4*>(g_tape)[(size_t)row * (C_ / 4) + tid];
        float s = x.x + x.y + x.z + x.w;
        float qq = x.x*x.x + x.y*x.y + x.z*x.z + x.w*x.w;
        #pragma unroll
        for (int o = 16; o; o >>= 1) {
            s  += __shfl_xor_sync(0xffffffffu, s, o);
            qq += __shfl_xor_sync(0xffffffffu, qq, o);
        }
        if (lane == 0) { sred[0][warp] = s; sred[1][warp] = qq; }
        __syncthreads();
        if (tid == 0) {
            float ts = 0.f, tq = 0.f;
            #pragma unroll
            for (int k = 0; k < 8; k++) { ts += sred[0][k]; tq += sred[1][k]; }
            float mu = ts * (1.f / C_);
            smv[0] = mu;
            smv[1] = rsqrtf(tq * (1.f / C_) - mu * mu + LN_EPS_);
        }
        __syncthreads();
        float mu = smv[0], rstd = smv[1];
        float4 h;
        h.x = (x.x - mu) * rstd * g4.x + e4.x;
        h.y = (x.y - mu) * rstd * g4.y + e4.y;
        h.z = (x.z - mu) * rstd * g4.z + e4.z;
        h.w = (x.w - mu) * rstd * g4.w + e4.w;
        #pragma unroll
        for (int v = 0; v < V_; v++) {
            float4 w = reinterpret_cast<const float4*>(sWo)[v * (C_ / 4) + tid];
            float pp = h.x*w.x + h.y*w.y + h.z*w.z + h.w*w.w;
            #pragma unroll
            for (int o = 16; o; o >>= 1) pp += __shfl_xor_sync(0xffffffffu, pp, o);
            if (lane == 0) sv2[warp][v] = pp;
        }
        __syncthreads();
        if (tid < V_) {
            float acc = bo[tid];
            #pragma unroll
            for (int k = 0; k < 8; k++) acc += sv2[k][tid];
            out[(size_t)row * V_ + tid] = acc;
        }
        __syncthreads();
    }
}

// ---------------------------------------------------------------------------
extern "C" void kernel_launch(void* const* d_in, const int* in_sizes, int n_in,
                              void* d_out, int out_size)
{
    const float* vals = (const float*)d_in[0];
    const float* Wd   = (const float*)d_in[1];
    const float* bd   = (const float*)d_in[2];
    const float* Wr   = (const float*)d_in[3];
    const float* br   = (const float*)d_in[4];
    const float* lng  = (const float*)d_in[5];
    const float* lnb  = (const float*)d_in[6];
    const float* Wo   = (const float*)d_in[7];
    const float* bo   = (const float*)d_in[8];
    float* out = (float*)d_out;

    const int SMEM_SCAN = (K_ * TS_ + K_ * TS_ + 8 * G_ * TS_ + 8 * 64 + K_) * 4;
    cudaFuncSetAttribute(scan_kernel,
                         cudaFuncAttributeMaxDynamicSharedMemorySize, SMEM_SCAN);

    heads_kernel<<<(S_ * B_) / 8, 256>>>(vals, Wd, bd, Wr, br);
    pos_kernel<<<B_ / 8, 256>>>();
    gramd_kernel<<<B_ * NQ_, 256>>>();
    scan_kernel<<<B_ * (C_ / TS_), 256, SMEM_SCAN>>>(vals);
    decode_kernel<<<(TS_ * B_) / 16, 256>>>(lng, lnb, Wo, bo, out);
}